// round 2
// baseline (speedup 1.0000x reference)
#include <cuda_runtime.h>
#include <math.h>

// Problem constants
#define NB 2
#define NV 5023
#define NF 2048
#define IH 256
#define IW 256
#define PP (IH * IW)

// Per-face precomputed SoA: [component][b*NF + f]
// 0:A0=y1-y2 1:B0=x2-x1 2:A1=y2-y0 3:B1=x0-x2 4:x2 5:y2 6:inv
// 7:z0 8:z1 9:z2 10:xmin 11:xmax 12:ymin 13:ymax 14:zmax
__device__ float g_face[15][NB * NF];
// Per-vertex sampled texture color
__device__ float g_vcol[NB * NV * 3];
// Packed, zmax-descending-sorted per-face records
__device__ float4 g_q0[NB * NF];  // A0,B0,A1,B1
__device__ float4 g_q1[NB * NF];  // x2,y2,inv,zmax
__device__ float4 g_q2[NB * NF];  // z0,z1,z2,face_id(bits)
__device__ float4 g_qb[NB * NF];  // xmin,xmax,ymin,ymax

__global__ void face_pre(const float* __restrict__ tv, const int* __restrict__ faces) {
    int idx = blockIdx.x * blockDim.x + threadIdx.x;
    if (idx >= NB * NF) return;
    int b = idx / NF, f = idx % NF;
    int i0 = faces[f * 3 + 0];
    int i1 = faces[f * 3 + 1];
    int i2 = faces[f * 3 + 2];
    const float* p0 = tv + ((size_t)b * NV + i0) * 3;
    const float* p1 = tv + ((size_t)b * NV + i1) * 3;
    const float* p2 = tv + ((size_t)b * NV + i2) * 3;
    float x0 = p0[0], y0 = p0[1], z0 = p0[2];
    float x1 = p1[0], y1 = p1[1], z1 = p1[2];
    float x2 = p2[0], y2 = p2[1], z2 = p2[2];

    float denom = (y1 - y2) * (x0 - x2) + (x2 - x1) * (y0 - y2);
    bool valid = fabsf(denom) > 1e-8f;
    float inv = valid ? (1.0f / denom) : 0.0f;

    g_face[0][idx] = y1 - y2;
    g_face[1][idx] = x2 - x1;
    g_face[2][idx] = y2 - y0;
    g_face[3][idx] = x0 - x2;
    g_face[4][idx] = x2;
    g_face[5][idx] = y2;
    g_face[6][idx] = inv;
    g_face[7][idx] = z0;
    g_face[8][idx] = z1;
    g_face[9][idx] = z2;

    float xmn = fminf(x0, fminf(x1, x2));
    float xmx = fmaxf(x0, fmaxf(x1, x2));
    float ymn = fminf(y0, fminf(y1, y2));
    float ymx = fmaxf(y0, fmaxf(y1, y2));
    float zmx = fmaxf(z0, fmaxf(z1, z2));
    if (!valid) { xmn = 2e30f; xmx = -2e30f; ymn = 2e30f; ymx = -2e30f; zmx = -3e30f; }
    g_face[10][idx] = xmn;
    g_face[11][idx] = xmx;
    g_face[12][idx] = ymn;
    g_face[13][idx] = ymx;
    g_face[14][idx] = zmx;
}

__global__ void vcol_pre(const float* __restrict__ tex, const float* __restrict__ uv) {
    int idx = blockIdx.x * blockDim.x + threadIdx.x;
    if (idx >= NB * NV) return;
    int b = idx / NV, v = idx % NV;
    float u = uv[v * 2 + 0] * 255.0f;
    float vv = uv[v * 2 + 1] * 255.0f;
    float u0f = floorf(u);
    float v0f = floorf(vv);
    u0f = fminf(fmaxf(u0f, 0.0f), 254.0f);
    v0f = fminf(fmaxf(v0f, 0.0f), 254.0f);
    int u0 = (int)u0f;
    int v0 = (int)v0f;
    float fu = u - u0f;
    float fv = vv - v0f;
    const float* t = tex + (size_t)b * 256 * 256 * 3;
    const float* r0 = t + ((size_t)v0 * 256 + u0) * 3;
    const float* r1 = t + ((size_t)(v0 + 1) * 256 + u0) * 3;
#pragma unroll
    for (int c = 0; c < 3; c++) {
        float c00 = r0[c];
        float c01 = r0[3 + c];
        float c10 = r1[c];
        float c11 = r1[3 + c];
        float top = c00 * (1.0f - fu) + c01 * fu;
        float bot = c10 * (1.0f - fu) + c11 * fu;
        g_vcol[idx * 3 + c] = top * (1.0f - fv) + bot * fv;
    }
}

// One block per batch: bitonic sort 2048 faces by zmax descending, then pack AoS.
__global__ void sortpack() {
    __shared__ float key[NF];
    __shared__ int   sidx[NF];
    const int b = blockIdx.x;
    for (int i = threadIdx.x; i < NF; i += blockDim.x) {
        key[i] = g_face[14][b * NF + i];
        sidx[i] = i;
    }
    __syncthreads();
    for (int k = 2; k <= NF; k <<= 1) {
        for (int j = k >> 1; j > 0; j >>= 1) {
            for (int i = threadIdx.x; i < NF; i += blockDim.x) {
                int ixj = i ^ j;
                if (ixj > i) {
                    bool desc = ((i & k) == 0);  // descending overall
                    float ki = key[i], kj = key[ixj];
                    bool doSwap = desc ? (ki < kj) : (ki > kj);
                    if (doSwap) {
                        key[i] = kj; key[ixj] = ki;
                        int t = sidx[i]; sidx[i] = sidx[ixj]; sidx[ixj] = t;
                    }
                }
            }
            __syncthreads();
        }
    }
    for (int r = threadIdx.x; r < NF; r += blockDim.x) {
        int f = sidx[r];
        int gi = b * NF + f;
        int go = b * NF + r;
        g_q0[go] = make_float4(g_face[0][gi], g_face[1][gi], g_face[2][gi], g_face[3][gi]);
        g_q1[go] = make_float4(g_face[4][gi], g_face[5][gi], g_face[6][gi], g_face[14][gi]);
        g_q2[go] = make_float4(g_face[7][gi], g_face[8][gi], g_face[9][gi], __int_as_float(f));
        g_qb[go] = make_float4(g_face[10][gi], g_face[11][gi], g_face[12][gi], g_face[13][gi]);
    }
}

#define TF 256  // faces per smem chunk

// 32x32 pixel tile per block, 16x16 threads, 2x2 pixels per thread.
__global__ void raster(const float* __restrict__ verts,
                       const int* __restrict__ faces,
                       float* __restrict__ out) {
    __shared__ float4 sQ0[TF], sQ1[TF], sQ2[TF];
    __shared__ int scount;
    __shared__ float schunkzmax;
    __shared__ float sred[256];

    const int b = blockIdx.z;
    const int tx = threadIdx.x, ty = threadIdx.y;
    const int tid = ty * 16 + tx;

    const int pxi0 = blockIdx.x * 32 + tx;
    const int pxi1 = pxi0 + 16;
    const int pyi0 = blockIdx.y * 32 + ty;
    const int pyi1 = pyi0 + 16;

    const float pxA = ((float)pxi0 + 0.5f) / 256.0f * 2.0f - 1.0f;
    const float pxB = ((float)pxi1 + 0.5f) / 256.0f * 2.0f - 1.0f;
    const float pyA = ((float)pyi0 + 0.5f) / 256.0f * 2.0f - 1.0f;
    const float pyB = ((float)pyi1 + 0.5f) / 256.0f * 2.0f - 1.0f;

    const float eps = 1e-4f;
    const float blk_xmin = (blockIdx.x * 32 + 0.5f)  / 256.0f * 2.0f - 1.0f - eps;
    const float blk_xmax = (blockIdx.x * 32 + 31.5f) / 256.0f * 2.0f - 1.0f + eps;
    const float blk_ymin = (blockIdx.y * 32 + 0.5f)  / 256.0f * 2.0f - 1.0f - eps;
    const float blk_ymax = (blockIdx.y * 32 + 31.5f) / 256.0f * 2.0f - 1.0f + eps;

    // per-pixel best state: order [ (xA,yA), (xB,yA), (xA,yB), (xB,yB) ]
    float bz[4], bw0[4], bw1[4], bw2[4];
    int bf[4];
#pragma unroll
    for (int p = 0; p < 4; p++) { bz[p] = -1.0f; bf[p] = -1; bw0[p] = 0.0f; bw1[p] = 0.0f; bw2[p] = 0.0f; }
    const float pxs[4] = { pxA, pxB, pxA, pxB };
    const float pys[4] = { pyA, pyA, pyB, pyB };

    float minbz = -1.0f;

    for (int base = 0; base < NF; base += TF) {
        if (tid == 0) {
            scount = 0;
            schunkzmax = g_q1[b * NF + base].w;
        }
        __syncthreads();
        // sred[0] still holds previous chunk's block-min bz (valid when base>0)
        if (base > 0 && schunkzmax < sred[0]) break;

        {
            int r = b * NF + base + tid;
            float4 qb = g_qb[r];
            if (qb.y >= blk_xmin && qb.x <= blk_xmax && qb.w >= blk_ymin && qb.z <= blk_ymax) {
                int slot = atomicAdd(&scount, 1);
                sQ0[slot] = g_q0[r];
                sQ1[slot] = g_q1[r];
                sQ2[slot] = g_q2[r];
            }
        }
        __syncthreads();

        const int cnt = scount;
        for (int j = 0; j < cnt; j++) {
            float4 q1 = sQ1[j];
            if (q1.w < minbz) continue;  // cannot beat or tie any of my pixels
            float4 q0 = sQ0[j];
            float4 q2 = sQ2[j];
            int f2 = __float_as_int(q2.w);
            const float inv = q1.z;
#pragma unroll
            for (int p = 0; p < 4; p++) {
                float dx = pxs[p] - q1.x;
                float dy = pys[p] - q1.y;
                float w0 = (q0.x * dx + q0.y * dy) * inv;
                float w1 = (q0.z * dx + q0.w * dy) * inv;
                float w2 = 1.0f - w0 - w1;
                if (w0 >= 0.0f && w1 >= 0.0f && w2 >= 0.0f) {
                    float z = w0 * q2.x + w1 * q2.y + w2 * q2.z;
                    // strict-> update; exact z tie -> lowest face index wins
                    if (z > bz[p] || (z == bz[p] && bf[p] >= 0 && f2 < bf[p])) {
                        bz[p] = z; bf[p] = f2;
                        bw0[p] = w0; bw1[p] = w1; bw2[p] = w2;
                    }
                }
            }
            minbz = fminf(fminf(bz[0], bz[1]), fminf(bz[2], bz[3]));
        }
        __syncthreads();

        // block-wide min bz for next chunk's break test
        sred[tid] = fminf(fminf(bz[0], bz[1]), fminf(bz[2], bz[3]));
        __syncthreads();
#pragma unroll
        for (int s = 128; s > 0; s >>= 1) {
            if (tid < s) sred[tid] = fminf(sred[tid], sred[tid + s]);
            __syncthreads();
        }
    }

    // ---- shading + stores (4 pixels per thread) ----
    float* rend = out;
    float* al   = out + (size_t)NB * 6 * PP;
    float* fo   = al  + (size_t)NB * PP;
    float* zo   = fo  + (size_t)NB * PP;

    const int pxi[4] = { pxi0, pxi1, pxi0, pxi1 };
    const int pyi[4] = { pyi0, pyi0, pyi1, pyi1 };
#pragma unroll
    for (int p = 0; p < 4; p++) {
        const int pix = pyi[p] * IW + pxi[p];
        const float alpha = (bf[p] >= 0) ? 1.0f : 0.0f;
        const int sf = (bf[p] >= 0) ? bf[p] : 0;
        const int i0 = faces[sf * 3 + 0];
        const int i1 = faces[sf * 3 + 1];
        const int i2 = faces[sf * 3 + 2];

        const float* c0 = &g_vcol[((size_t)b * NV + i0) * 3];
        const float* c1 = &g_vcol[((size_t)b * NV + i1) * 3];
        const float* c2 = &g_vcol[((size_t)b * NV + i2) * 3];
        const float* v0 = verts + ((size_t)b * NV + i0) * 3;
        const float* v1 = verts + ((size_t)b * NV + i1) * 3;
        const float* v2 = verts + ((size_t)b * NV + i2) * 3;

        float ch[6];
#pragma unroll
        for (int c = 0; c < 3; c++)
            ch[c] = c0[c] * bw0[p] + c1[c] * bw1[p] + c2[c] * bw2[p];
#pragma unroll
        for (int c = 0; c < 3; c++)
            ch[3 + c] = v0[c] * bw0[p] + v1[c] * bw1[p] + v2[c] * bw2[p];

#pragma unroll
        for (int c = 0; c < 6; c++)
            rend[((size_t)b * 6 + c) * PP + pix] = ch[c] * alpha;
        al[(size_t)b * PP + pix] = alpha;
        fo[(size_t)b * PP + pix] = (float)bf[p];
        zo[(size_t)b * PP + pix] = bz[p];
    }
}

extern "C" void kernel_launch(void* const* d_in, const int* in_sizes, int n_in,
                              void* d_out, int out_size) {
    const float* vertices = (const float*)d_in[0];
    const float* tverts   = (const float*)d_in[1];
    const float* tex      = (const float*)d_in[2];
    const float* uv       = (const float*)d_in[3];
    const int*   faces    = (const int*)d_in[4];
    float* out = (float*)d_out;

    face_pre<<<(NB * NF + 255) / 256, 256>>>(tverts, faces);
    vcol_pre<<<(NB * NV + 255) / 256, 256>>>(tex, uv);
    sortpack<<<NB, 1024>>>();
    dim3 grid(IW / 32, IH / 32, NB);
    dim3 blk(16, 16);
    raster<<<grid, blk>>>(vertices, faces, out);
}

// round 3
// speedup vs baseline: 1.5322x; 1.5322x over previous
#include <cuda_runtime.h>
#include <math.h>

// Problem constants
#define NB 2
#define NV 5023
#define NF 2048
#define IH 256
#define IW 256
#define PP (IH * IW)

// Per-face precomputed SoA: [component][b*NF + f]
// 0:A0 1:B0 2:A1 3:B1 4:x2 5:y2 6:inv 7:z0 8:z1 9:z2 10:xmin 11:xmax 12:ymin 13:ymax 14:zmax
__device__ float g_face[15][NB * NF];
__device__ float g_vcol[NB * NV * 3];
// Packed, zmax-descending-sorted per-face records
__device__ float4 g_q0[NB * NF];  // A0,B0,A1,B1
__device__ float4 g_q1[NB * NF];  // x2,y2,inv,zmax
__device__ float4 g_q2[NB * NF];  // z0,z1,z2,face_id(bits)
__device__ float4 g_qb[NB * NF];  // xmin,xmax,ymin,ymax

__global__ void face_pre(const float* __restrict__ tv, const int* __restrict__ faces) {
    int idx = blockIdx.x * blockDim.x + threadIdx.x;
    if (idx >= NB * NF) return;
    int b = idx / NF, f = idx % NF;
    int i0 = faces[f * 3 + 0];
    int i1 = faces[f * 3 + 1];
    int i2 = faces[f * 3 + 2];
    const float* p0 = tv + ((size_t)b * NV + i0) * 3;
    const float* p1 = tv + ((size_t)b * NV + i1) * 3;
    const float* p2 = tv + ((size_t)b * NV + i2) * 3;
    float x0 = p0[0], y0 = p0[1], z0 = p0[2];
    float x1 = p1[0], y1 = p1[1], z1 = p1[2];
    float x2 = p2[0], y2 = p2[1], z2 = p2[2];

    float denom = (y1 - y2) * (x0 - x2) + (x2 - x1) * (y0 - y2);
    bool valid = fabsf(denom) > 1e-8f;
    float inv = valid ? (1.0f / denom) : 0.0f;

    g_face[0][idx] = y1 - y2;
    g_face[1][idx] = x2 - x1;
    g_face[2][idx] = y2 - y0;
    g_face[3][idx] = x0 - x2;
    g_face[4][idx] = x2;
    g_face[5][idx] = y2;
    g_face[6][idx] = inv;
    g_face[7][idx] = z0;
    g_face[8][idx] = z1;
    g_face[9][idx] = z2;

    float xmn = fminf(x0, fminf(x1, x2));
    float xmx = fmaxf(x0, fmaxf(x1, x2));
    float ymn = fminf(y0, fminf(y1, y2));
    float ymx = fmaxf(y0, fmaxf(y1, y2));
    float zmx = fmaxf(z0, fmaxf(z1, z2));
    if (!valid) { xmn = 2e30f; xmx = -2e30f; ymn = 2e30f; ymx = -2e30f; zmx = -3e30f; }
    g_face[10][idx] = xmn;
    g_face[11][idx] = xmx;
    g_face[12][idx] = ymn;
    g_face[13][idx] = ymx;
    g_face[14][idx] = zmx;
}

__global__ void vcol_pre(const float* __restrict__ tex, const float* __restrict__ uv) {
    int idx = blockIdx.x * blockDim.x + threadIdx.x;
    if (idx >= NB * NV) return;
    int b = idx / NV, v = idx % NV;
    float u = uv[v * 2 + 0] * 255.0f;
    float vv = uv[v * 2 + 1] * 255.0f;
    float u0f = floorf(u);
    float v0f = floorf(vv);
    u0f = fminf(fmaxf(u0f, 0.0f), 254.0f);
    v0f = fminf(fmaxf(v0f, 0.0f), 254.0f);
    int u0 = (int)u0f;
    int v0 = (int)v0f;
    float fu = u - u0f;
    float fv = vv - v0f;
    const float* t = tex + (size_t)b * 256 * 256 * 3;
    const float* r0 = t + ((size_t)v0 * 256 + u0) * 3;
    const float* r1 = t + ((size_t)(v0 + 1) * 256 + u0) * 3;
#pragma unroll
    for (int c = 0; c < 3; c++) {
        float c00 = r0[c];
        float c01 = r0[3 + c];
        float c10 = r1[c];
        float c11 = r1[3 + c];
        float top = c00 * (1.0f - fu) + c01 * fu;
        float bot = c10 * (1.0f - fu) + c11 * fu;
        g_vcol[idx * 3 + c] = top * (1.0f - fv) + bot * fv;
    }
}

// One block per batch: bitonic sort faces by zmax descending, then pack AoS.
__global__ void sortpack() {
    __shared__ float key[NF];
    __shared__ int   sidx[NF];
    const int b = blockIdx.x;
    for (int i = threadIdx.x; i < NF; i += blockDim.x) {
        key[i] = g_face[14][b * NF + i];
        sidx[i] = i;
    }
    __syncthreads();
    for (int k = 2; k <= NF; k <<= 1) {
        for (int j = k >> 1; j > 0; j >>= 1) {
            for (int i = threadIdx.x; i < NF; i += blockDim.x) {
                int ixj = i ^ j;
                if (ixj > i) {
                    bool desc = ((i & k) == 0);
                    float ki = key[i], kj = key[ixj];
                    bool doSwap = desc ? (ki < kj) : (ki > kj);
                    if (doSwap) {
                        key[i] = kj; key[ixj] = ki;
                        int t = sidx[i]; sidx[i] = sidx[ixj]; sidx[ixj] = t;
                    }
                }
            }
            __syncthreads();
        }
    }
    for (int r = threadIdx.x; r < NF; r += blockDim.x) {
        int f = sidx[r];
        int gi = b * NF + f;
        int go = b * NF + r;
        g_q0[go] = make_float4(g_face[0][gi], g_face[1][gi], g_face[2][gi], g_face[3][gi]);
        g_q1[go] = make_float4(g_face[4][gi], g_face[5][gi], g_face[6][gi], g_face[14][gi]);
        g_q2[go] = make_float4(g_face[7][gi], g_face[8][gi], g_face[9][gi], __int_as_float(f));
        g_qb[go] = make_float4(g_face[10][gi], g_face[11][gi], g_face[12][gi], g_face[13][gi]);
    }
}

#define TF 256  // faces per smem chunk
#define NTHR 128

// 16x16 pixel tile per block, 128 threads, 2 pixels per thread (y and y+8).
__global__ void __launch_bounds__(NTHR) raster(const float* __restrict__ verts,
                                               const int* __restrict__ faces,
                                               float* __restrict__ out) {
    __shared__ float4 sQ0[TF], sQ1[TF], sQ2[TF];
    __shared__ int scount;
    __shared__ float swred[4];
    __shared__ float sblockmin;

    const int b = blockIdx.z;
    const int tid = threadIdx.x;
    const int tx = tid & 15;
    const int ty = tid >> 4;  // 0..7

    const int pxi = blockIdx.x * 16 + tx;
    const int pyi0 = blockIdx.y * 16 + ty;
    const int pyi1 = pyi0 + 8;

    const float px  = ((float)pxi + 0.5f) / 256.0f * 2.0f - 1.0f;
    const float pyA = ((float)pyi0 + 0.5f) / 256.0f * 2.0f - 1.0f;
    const float pyB = ((float)pyi1 + 0.5f) / 256.0f * 2.0f - 1.0f;

    const float eps = 1e-4f;
    const float blk_xmin = (blockIdx.x * 16 + 0.5f)  / 256.0f * 2.0f - 1.0f - eps;
    const float blk_xmax = (blockIdx.x * 16 + 15.5f) / 256.0f * 2.0f - 1.0f + eps;
    const float blk_ymin = (blockIdx.y * 16 + 0.5f)  / 256.0f * 2.0f - 1.0f - eps;
    const float blk_ymax = (blockIdx.y * 16 + 15.5f) / 256.0f * 2.0f - 1.0f + eps;

    float bz0 = -1.0f, bz1 = -1.0f;
    int bf0 = -1, bf1 = -1;
    float w00 = 0.0f, w01 = 0.0f, w02 = 0.0f;
    float w10 = 0.0f, w11 = 0.0f, w12 = 0.0f;
    float minbz = -1.0f;

    for (int base = 0; base < NF; base += TF) {
        if (tid == 0) scount = 0;
        __syncthreads();
        if (base > 0 && g_q1[b * NF + base].w < sblockmin) break;

        // compaction: 2 faces per thread
#pragma unroll
        for (int k = 0; k < TF / NTHR; k++) {
            int r = b * NF + base + tid + k * NTHR;
            float4 qb = g_qb[r];
            if (qb.y >= blk_xmin && qb.x <= blk_xmax && qb.w >= blk_ymin && qb.z <= blk_ymax) {
                int slot = atomicAdd(&scount, 1);
                sQ0[slot] = g_q0[r];
                sQ1[slot] = g_q1[r];
                sQ2[slot] = g_q2[r];
            }
        }
        __syncthreads();

        const int cnt = scount;
        for (int j = 0; j < cnt; j++) {
            float4 q1 = sQ1[j];
            if (q1.w < minbz) continue;  // can't beat or tie either pixel
            float4 q0 = sQ0[j];
            float4 q2 = sQ2[j];
            int f2 = __float_as_int(q2.w);
            const float inv = q1.z;
            const float dx = px - q1.x;
            bool upd = false;
            {
                float dy = pyA - q1.y;
                float w0 = (q0.x * dx + q0.y * dy) * inv;
                float w1 = (q0.z * dx + q0.w * dy) * inv;
                float w2 = 1.0f - w0 - w1;
                if (w0 >= 0.0f && w1 >= 0.0f && w2 >= 0.0f) {
                    float z = w0 * q2.x + w1 * q2.y + w2 * q2.z;
                    if (z > bz0 || (z == bz0 && bf0 >= 0 && f2 < bf0)) {
                        bz0 = z; bf0 = f2; w00 = w0; w01 = w1; w02 = w2; upd = true;
                    }
                }
            }
            {
                float dy = pyB - q1.y;
                float w0 = (q0.x * dx + q0.y * dy) * inv;
                float w1 = (q0.z * dx + q0.w * dy) * inv;
                float w2 = 1.0f - w0 - w1;
                if (w0 >= 0.0f && w1 >= 0.0f && w2 >= 0.0f) {
                    float z = w0 * q2.x + w1 * q2.y + w2 * q2.z;
                    if (z > bz1 || (z == bz1 && bf1 >= 0 && f2 < bf1)) {
                        bz1 = z; bf1 = f2; w10 = w0; w11 = w1; w12 = w2; upd = true;
                    }
                }
            }
            if (upd) minbz = fminf(bz0, bz1);
        }

        // block-wide min bz for next chunk's break test (warp shuffle + 4 smem)
        float v = minbz;
#pragma unroll
        for (int s = 16; s > 0; s >>= 1)
            v = fminf(v, __shfl_xor_sync(0xffffffffu, v, s));
        if ((tid & 31) == 0) swred[tid >> 5] = v;
        __syncthreads();
        if (tid == 0)
            sblockmin = fminf(fminf(swred[0], swred[1]), fminf(swred[2], swred[3]));
        __syncthreads();
    }

    // ---- shading + stores (2 pixels per thread) ----
    float* rend = out;
    float* al   = out + (size_t)NB * 6 * PP;
    float* fo   = al  + (size_t)NB * PP;
    float* zo   = fo  + (size_t)NB * PP;

    float bzs[2] = { bz0, bz1 };
    int   bfs[2] = { bf0, bf1 };
    float bws0[2] = { w00, w10 };
    float bws1[2] = { w01, w11 };
    float bws2[2] = { w02, w12 };
    const int pyis[2] = { pyi0, pyi1 };

#pragma unroll
    for (int p = 0; p < 2; p++) {
        const int pix = pyis[p] * IW + pxi;
        const float alpha = (bfs[p] >= 0) ? 1.0f : 0.0f;
        const int sf = (bfs[p] >= 0) ? bfs[p] : 0;
        const int i0 = faces[sf * 3 + 0];
        const int i1 = faces[sf * 3 + 1];
        const int i2 = faces[sf * 3 + 2];

        const float* c0 = &g_vcol[((size_t)b * NV + i0) * 3];
        const float* c1 = &g_vcol[((size_t)b * NV + i1) * 3];
        const float* c2 = &g_vcol[((size_t)b * NV + i2) * 3];
        const float* v0 = verts + ((size_t)b * NV + i0) * 3;
        const float* v1 = verts + ((size_t)b * NV + i1) * 3;
        const float* v2 = verts + ((size_t)b * NV + i2) * 3;

        float ch[6];
#pragma unroll
        for (int c = 0; c < 3; c++)
            ch[c] = c0[c] * bws0[p] + c1[c] * bws1[p] + c2[c] * bws2[p];
#pragma unroll
        for (int c = 0; c < 3; c++)
            ch[3 + c] = v0[c] * bws0[p] + v1[c] * bws1[p] + v2[c] * bws2[p];

#pragma unroll
        for (int c = 0; c < 6; c++)
            rend[((size_t)b * 6 + c) * PP + pix] = ch[c] * alpha;
        al[(size_t)b * PP + pix] = alpha;
        fo[(size_t)b * PP + pix] = (float)bfs[p];
        zo[(size_t)b * PP + pix] = bzs[p];
    }
}

extern "C" void kernel_launch(void* const* d_in, const int* in_sizes, int n_in,
                              void* d_out, int out_size) {
    const float* vertices = (const float*)d_in[0];
    const float* tverts   = (const float*)d_in[1];
    const float* tex      = (const float*)d_in[2];
    const float* uv       = (const float*)d_in[3];
    const int*   faces    = (const int*)d_in[4];
    float* out = (float*)d_out;

    face_pre<<<(NB * NF + 255) / 256, 256>>>(tverts, faces);
    vcol_pre<<<(NB * NV + 255) / 256, 256>>>(tex, uv);
    sortpack<<<NB, 1024>>>();
    dim3 grid(IW / 16, IH / 16, NB);
    raster<<<grid, NTHR>>>(vertices, faces, out);
}

// round 4
// speedup vs baseline: 2.6083x; 1.7024x over previous
#include <cuda_runtime.h>
#include <math.h>

// Problem constants
#define NB 2
#define NV 5023
#define NF 2048
#define IH 256
#define IW 256
#define PP (IH * IW)
#define TF 256               // faces per smem chunk
#define NCHUNK (NF / TF)     // 8
#define NTHR 128

// Per-face precomputed SoA: [component][b*NF + f]
// 0:A0 1:B0 2:A1 3:B1 4:x2 5:y2 6:inv 7:z0 8:z1 9:z2 10:xmin 11:xmax 12:ymin 13:ymax 14:zmax
__device__ float g_face[15][NB * NF];
__device__ float g_vcol[NB * NV * 3];
// Packed, approx-zmax-descending per-face records
__device__ float4 g_q0[NB * NF];  // A0,B0,A1,B1
__device__ float4 g_q1[NB * NF];  // x2,y2,inv,zmax
__device__ float4 g_q2[NB * NF];  // z0,z1,z2,face_id(bits)
__device__ float4 g_qb[NB * NF];  // xmin,xmax,ymin,ymax
// Suffix-max zmax bound per chunk: bound[c] >= zmax of every face in chunks >= c
__device__ float g_chunkbound[NB * NCHUNK];

// ---- fused prep: per-face coefficients + per-vertex texture sample ----
__global__ void prep(const float* __restrict__ tv, const int* __restrict__ faces,
                     const float* __restrict__ tex, const float* __restrict__ uv) {
    int idx = blockIdx.x * blockDim.x + threadIdx.x;

    if (idx < NB * NF) {
        int b = idx / NF, f = idx % NF;
        int i0 = faces[f * 3 + 0];
        int i1 = faces[f * 3 + 1];
        int i2 = faces[f * 3 + 2];
        const float* p0 = tv + ((size_t)b * NV + i0) * 3;
        const float* p1 = tv + ((size_t)b * NV + i1) * 3;
        const float* p2 = tv + ((size_t)b * NV + i2) * 3;
        float x0 = p0[0], y0 = p0[1], z0 = p0[2];
        float x1 = p1[0], y1 = p1[1], z1 = p1[2];
        float x2 = p2[0], y2 = p2[1], z2 = p2[2];

        float denom = (y1 - y2) * (x0 - x2) + (x2 - x1) * (y0 - y2);
        bool valid = fabsf(denom) > 1e-8f;
        float inv = valid ? (1.0f / denom) : 0.0f;

        g_face[0][idx] = y1 - y2;
        g_face[1][idx] = x2 - x1;
        g_face[2][idx] = y2 - y0;
        g_face[3][idx] = x0 - x2;
        g_face[4][idx] = x2;
        g_face[5][idx] = y2;
        g_face[6][idx] = inv;
        g_face[7][idx] = z0;
        g_face[8][idx] = z1;
        g_face[9][idx] = z2;

        float xmn = fminf(x0, fminf(x1, x2));
        float xmx = fmaxf(x0, fmaxf(x1, x2));
        float ymn = fminf(y0, fminf(y1, y2));
        float ymx = fmaxf(y0, fmaxf(y1, y2));
        float zmx = fmaxf(z0, fmaxf(z1, z2));
        if (!valid) { xmn = 2e30f; xmx = -2e30f; ymn = 2e30f; ymx = -2e30f; zmx = -3e30f; }
        g_face[10][idx] = xmn;
        g_face[11][idx] = xmx;
        g_face[12][idx] = ymn;
        g_face[13][idx] = ymx;
        g_face[14][idx] = zmx;
    }

    if (idx < NB * NV) {
        int b = idx / NV, v = idx % NV;
        float u = uv[v * 2 + 0] * 255.0f;
        float vv = uv[v * 2 + 1] * 255.0f;
        float u0f = floorf(u);
        float v0f = floorf(vv);
        u0f = fminf(fmaxf(u0f, 0.0f), 254.0f);
        v0f = fminf(fmaxf(v0f, 0.0f), 254.0f);
        int u0 = (int)u0f;
        int v0 = (int)v0f;
        float fu = u - u0f;
        float fv = vv - v0f;
        const float* t = tex + (size_t)b * 256 * 256 * 3;
        const float* r0 = t + ((size_t)v0 * 256 + u0) * 3;
        const float* r1 = t + ((size_t)(v0 + 1) * 256 + u0) * 3;
#pragma unroll
        for (int c = 0; c < 3; c++) {
            float c00 = r0[c];
            float c01 = r0[3 + c];
            float c10 = r1[c];
            float c11 = r1[3 + c];
            float top = c00 * (1.0f - fu) + c01 * fu;
            float bot = c10 * (1.0f - fu) + c11 * fu;
            g_vcol[idx * 3 + c] = top * (1.0f - fv) + bot * fv;
        }
    }
}

// ---- counting sort by zmax (descending, 256 buckets), pack AoS, chunk bounds ----
__device__ __forceinline__ int zbucket(float zmx) {
    // zmax in (-1,1) for valid faces; invalid (-3e30) clamps to 255.
    int bi = (int)((1.0f - zmx) * 127.5f);
    return min(max(bi, 0), 255);
}

__global__ void sortpack() {
    __shared__ int hist[256];
    __shared__ int offs[256];
    __shared__ unsigned schunkmax[NCHUNK];  // ordered-encoded float
    const int b = blockIdx.x;
    const int tid = threadIdx.x;

    if (tid < 256) { hist[tid] = 0; }
    if (tid < NCHUNK) schunkmax[tid] = 0u;
    __syncthreads();

    for (int i = tid; i < NF; i += blockDim.x) {
        int bi = zbucket(g_face[14][b * NF + i]);
        atomicAdd(&hist[bi], 1);
    }
    __syncthreads();

    // exclusive prefix over 256 buckets (Hillis-Steele on 256 threads)
    if (tid < 256) offs[tid] = hist[tid];
    __syncthreads();
#pragma unroll
    for (int s = 1; s < 256; s <<= 1) {
        int v = 0;
        if (tid < 256 && tid >= s) v = offs[tid - s];
        __syncthreads();
        if (tid < 256) offs[tid] += v;
        __syncthreads();
    }
    // convert inclusive -> exclusive
    int myExcl = 0;
    if (tid < 256) myExcl = offs[tid] - hist[tid];
    __syncthreads();
    if (tid < 256) offs[tid] = myExcl;
    __syncthreads();

    // scatter
    for (int i = tid; i < NF; i += blockDim.x) {
        int gi = b * NF + i;
        float zmx = g_face[14][gi];
        int bi = zbucket(zmx);
        int pos = atomicAdd(&offs[bi], 1);
        int go = b * NF + pos;
        g_q0[go] = make_float4(g_face[0][gi], g_face[1][gi], g_face[2][gi], g_face[3][gi]);
        g_q1[go] = make_float4(g_face[4][gi], g_face[5][gi], g_face[6][gi], zmx);
        g_q2[go] = make_float4(g_face[7][gi], g_face[8][gi], g_face[9][gi], __int_as_float(i));
        g_qb[go] = make_float4(g_face[10][gi], g_face[11][gi], g_face[12][gi], g_face[13][gi]);
        // ordered encoding for float atomicMax on unsigned
        unsigned ub = __float_as_uint(zmx);
        unsigned enc = (ub & 0x80000000u) ? ~ub : (ub | 0x80000000u);
        atomicMax(&schunkmax[pos / TF], enc);
    }
    __syncthreads();

    if (tid == 0) {
        // suffix max -> monotone non-increasing bound
        float bound = -3e30f;
        for (int c = NCHUNK - 1; c >= 0; c--) {
            unsigned enc = schunkmax[c];
            unsigned ub = (enc & 0x80000000u) ? (enc & 0x7FFFFFFFu) : ~enc;
            float zm = __uint_as_float(ub);
            bound = fmaxf(bound, zm);
            g_chunkbound[b * NCHUNK + c] = bound;
        }
    }
}

// ---- raster: 16x8 pixel tile per block, 128 threads, 1 pixel per thread ----
__global__ void __launch_bounds__(NTHR) raster(const float* __restrict__ verts,
                                               const int* __restrict__ faces,
                                               float* __restrict__ out) {
    __shared__ float4 sQ0[TF], sQ1[TF], sQ2[TF];
    __shared__ int scount;
    __shared__ float swred[4];
    __shared__ float sblockmin;

    const int b = blockIdx.z;
    const int tid = threadIdx.x;
    const int tx = tid & 15;
    const int ty = tid >> 4;  // 0..7

    const int pxi = blockIdx.x * 16 + tx;
    const int pyi = blockIdx.y * 8 + ty;

    const float px = ((float)pxi + 0.5f) / 256.0f * 2.0f - 1.0f;
    const float py = ((float)pyi + 0.5f) / 256.0f * 2.0f - 1.0f;

    const float eps = 1e-4f;
    const float blk_xmin = (blockIdx.x * 16 + 0.5f)  / 256.0f * 2.0f - 1.0f - eps;
    const float blk_xmax = (blockIdx.x * 16 + 15.5f) / 256.0f * 2.0f - 1.0f + eps;
    const float blk_ymin = (blockIdx.y * 8 + 0.5f)   / 256.0f * 2.0f - 1.0f - eps;
    const float blk_ymax = (blockIdx.y * 8 + 7.5f)   / 256.0f * 2.0f - 1.0f + eps;

    float bz = -1.0f;
    int bf = -1;
    float bw0 = 0.0f, bw1 = 0.0f, bw2 = 0.0f;

    for (int base = 0; base < NF; base += TF) {
        if (tid == 0) scount = 0;
        __syncthreads();
        if (base > 0 && g_chunkbound[b * NCHUNK + base / TF] < sblockmin) break;

        // compaction: 2 faces per thread
#pragma unroll
        for (int k = 0; k < TF / NTHR; k++) {
            int r = b * NF + base + tid + k * NTHR;
            float4 qb = g_qb[r];
            if (qb.y >= blk_xmin && qb.x <= blk_xmax && qb.w >= blk_ymin && qb.z <= blk_ymax) {
                int slot = atomicAdd(&scount, 1);
                sQ0[slot] = g_q0[r];
                sQ1[slot] = g_q1[r];
                sQ2[slot] = g_q2[r];
            }
        }
        __syncthreads();

        const int cnt = scount;
        for (int j = 0; j < cnt; j++) {
            float4 q1 = sQ1[j];
            if (q1.w < bz) continue;  // face can't beat or tie this pixel
            float4 q0 = sQ0[j];
            float4 q2 = sQ2[j];
            const float inv = q1.z;
            const float dx = px - q1.x;
            const float dy = py - q1.y;
            float w0 = (q0.x * dx + q0.y * dy) * inv;
            float w1 = (q0.z * dx + q0.w * dy) * inv;
            float w2 = 1.0f - w0 - w1;
            if (w0 >= 0.0f && w1 >= 0.0f && w2 >= 0.0f) {
                float z = w0 * q2.x + w1 * q2.y + w2 * q2.z;
                int f2 = __float_as_int(q2.w);
                // strict-> update; exact z tie -> lowest face index wins
                if (z > bz || (z == bz && bf >= 0 && f2 < bf)) {
                    bz = z; bf = f2;
                    bw0 = w0; bw1 = w1; bw2 = w2;
                }
            }
        }

        // block-wide min bz for next chunk's break test
        float v = bz;
#pragma unroll
        for (int s = 16; s > 0; s >>= 1)
            v = fminf(v, __shfl_xor_sync(0xffffffffu, v, s));
        if ((tid & 31) == 0) swred[tid >> 5] = v;
        __syncthreads();
        if (tid == 0)
            sblockmin = fminf(fminf(swred[0], swred[1]), fminf(swred[2], swred[3]));
        __syncthreads();
    }

    // ---- shading + store ----
    float* rend = out;
    float* al   = out + (size_t)NB * 6 * PP;
    float* fo   = al  + (size_t)NB * PP;
    float* zo   = fo  + (size_t)NB * PP;

    const int pix = pyi * IW + pxi;
    const float alpha = (bf >= 0) ? 1.0f : 0.0f;
    const int sf = (bf >= 0) ? bf : 0;
    const int i0 = faces[sf * 3 + 0];
    const int i1 = faces[sf * 3 + 1];
    const int i2 = faces[sf * 3 + 2];

    const float* c0 = &g_vcol[((size_t)b * NV + i0) * 3];
    const float* c1 = &g_vcol[((size_t)b * NV + i1) * 3];
    const float* c2 = &g_vcol[((size_t)b * NV + i2) * 3];
    const float* v0 = verts + ((size_t)b * NV + i0) * 3;
    const float* v1 = verts + ((size_t)b * NV + i1) * 3;
    const float* v2 = verts + ((size_t)b * NV + i2) * 3;

    float ch[6];
#pragma unroll
    for (int c = 0; c < 3; c++)
        ch[c] = c0[c] * bw0 + c1[c] * bw1 + c2[c] * bw2;
#pragma unroll
    for (int c = 0; c < 3; c++)
        ch[3 + c] = v0[c] * bw0 + v1[c] * bw1 + v2[c] * bw2;

#pragma unroll
    for (int c = 0; c < 6; c++)
        rend[((size_t)b * 6 + c) * PP + pix] = ch[c] * alpha;
    al[(size_t)b * PP + pix] = alpha;
    fo[(size_t)b * PP + pix] = (float)bf;
    zo[(size_t)b * PP + pix] = bz;
}

extern "C" void kernel_launch(void* const* d_in, const int* in_sizes, int n_in,
                              void* d_out, int out_size) {
    const float* vertices = (const float*)d_in[0];
    const float* tverts   = (const float*)d_in[1];
    const float* tex      = (const float*)d_in[2];
    const float* uv       = (const float*)d_in[3];
    const int*   faces    = (const int*)d_in[4];
    float* out = (float*)d_out;

    prep<<<(NB * NV + 255) / 256, 256>>>(tverts, faces, tex, uv);
    sortpack<<<NB, 1024>>>();
    dim3 grid(IW / 16, IH / 8, NB);
    raster<<<grid, NTHR>>>(vertices, faces, out);
}

// round 5
// speedup vs baseline: 3.5040x; 1.3434x over previous
#include <cuda_runtime.h>
#include <math.h>

// Problem constants
#define NB 2
#define NV 5023
#define NF 2048
#define IH 256
#define IW 256
#define PP (IH * IW)
#define TF 256               // faces per smem chunk
#define NCHUNK (NF / TF)     // 8
#define NTHR 128

// Per-face precomputed SoA: [component][b*NF + f]
// 0:A0 1:B0 2:A1 3:B1 4:x2 5:y2 6:inv 7:z0 8:z1 9:z2 10:xmin 11:xmax 12:ymin 13:ymax 14:zmax
__device__ float g_face[15][NB * NF];
__device__ float g_vcol[NB * NV * 3];
// Packed, approx-zmax-descending per-face records
__device__ float4 g_q0[NB * NF];  // A0,B0,A1,B1
__device__ float4 g_q1[NB * NF];  // x2,y2,inv,zmax
__device__ float4 g_q2[NB * NF];  // z0,z1,z2,face_id(bits)
__device__ float4 g_qb[NB * NF];  // xmin,xmax,ymin,ymax
// Suffix-max zmax bound per chunk
__device__ float g_chunkbound[NB * NCHUNK];

// ---- fused prep ----
__global__ void prep(const float* __restrict__ tv, const int* __restrict__ faces,
                     const float* __restrict__ tex, const float* __restrict__ uv) {
    int idx = blockIdx.x * blockDim.x + threadIdx.x;

    if (idx < NB * NF) {
        int b = idx / NF, f = idx % NF;
        int i0 = faces[f * 3 + 0];
        int i1 = faces[f * 3 + 1];
        int i2 = faces[f * 3 + 2];
        const float* p0 = tv + ((size_t)b * NV + i0) * 3;
        const float* p1 = tv + ((size_t)b * NV + i1) * 3;
        const float* p2 = tv + ((size_t)b * NV + i2) * 3;
        float x0 = p0[0], y0 = p0[1], z0 = p0[2];
        float x1 = p1[0], y1 = p1[1], z1 = p1[2];
        float x2 = p2[0], y2 = p2[1], z2 = p2[2];

        float denom = (y1 - y2) * (x0 - x2) + (x2 - x1) * (y0 - y2);
        bool valid = fabsf(denom) > 1e-8f;
        float inv = valid ? (1.0f / denom) : 0.0f;

        g_face[0][idx] = y1 - y2;
        g_face[1][idx] = x2 - x1;
        g_face[2][idx] = y2 - y0;
        g_face[3][idx] = x0 - x2;
        g_face[4][idx] = x2;
        g_face[5][idx] = y2;
        g_face[6][idx] = inv;
        g_face[7][idx] = z0;
        g_face[8][idx] = z1;
        g_face[9][idx] = z2;

        float xmn = fminf(x0, fminf(x1, x2));
        float xmx = fmaxf(x0, fmaxf(x1, x2));
        float ymn = fminf(y0, fminf(y1, y2));
        float ymx = fmaxf(y0, fmaxf(y1, y2));
        float zmx = fmaxf(z0, fmaxf(z1, z2));
        if (!valid) { xmn = 2e30f; xmx = -2e30f; ymn = 2e30f; ymx = -2e30f; zmx = -3e30f; }
        g_face[10][idx] = xmn;
        g_face[11][idx] = xmx;
        g_face[12][idx] = ymn;
        g_face[13][idx] = ymx;
        g_face[14][idx] = zmx;
    }

    if (idx < NB * NV) {
        int b = idx / NV, v = idx % NV;
        float u = uv[v * 2 + 0] * 255.0f;
        float vv = uv[v * 2 + 1] * 255.0f;
        float u0f = floorf(u);
        float v0f = floorf(vv);
        u0f = fminf(fmaxf(u0f, 0.0f), 254.0f);
        v0f = fminf(fmaxf(v0f, 0.0f), 254.0f);
        int u0 = (int)u0f;
        int v0 = (int)v0f;
        float fu = u - u0f;
        float fv = vv - v0f;
        const float* t = tex + (size_t)b * 256 * 256 * 3;
        const float* r0 = t + ((size_t)v0 * 256 + u0) * 3;
        const float* r1 = t + ((size_t)(v0 + 1) * 256 + u0) * 3;
#pragma unroll
        for (int c = 0; c < 3; c++) {
            float c00 = r0[c];
            float c01 = r0[3 + c];
            float c10 = r1[c];
            float c11 = r1[3 + c];
            float top = c00 * (1.0f - fu) + c01 * fu;
            float bot = c10 * (1.0f - fu) + c11 * fu;
            g_vcol[idx * 3 + c] = top * (1.0f - fv) + bot * fv;
        }
    }
}

// ---- counting sort by zmax (descending, 256 buckets), pack AoS, chunk bounds ----
__device__ __forceinline__ int zbucket(float zmx) {
    int bi = (int)((1.0f - zmx) * 127.5f);
    return min(max(bi, 0), 255);
}

__global__ void sortpack() {
    __shared__ int hist[256];
    __shared__ int offs[256];
    __shared__ unsigned schunkmax[NCHUNK];
    const int b = blockIdx.x;
    const int tid = threadIdx.x;

    if (tid < 256) { hist[tid] = 0; }
    if (tid < NCHUNK) schunkmax[tid] = 0u;
    __syncthreads();

    for (int i = tid; i < NF; i += blockDim.x) {
        int bi = zbucket(g_face[14][b * NF + i]);
        atomicAdd(&hist[bi], 1);
    }
    __syncthreads();

    if (tid < 256) offs[tid] = hist[tid];
    __syncthreads();
#pragma unroll
    for (int s = 1; s < 256; s <<= 1) {
        int v = 0;
        if (tid < 256 && tid >= s) v = offs[tid - s];
        __syncthreads();
        if (tid < 256) offs[tid] += v;
        __syncthreads();
    }
    int myExcl = 0;
    if (tid < 256) myExcl = offs[tid] - hist[tid];
    __syncthreads();
    if (tid < 256) offs[tid] = myExcl;
    __syncthreads();

    for (int i = tid; i < NF; i += blockDim.x) {
        int gi = b * NF + i;
        float zmx = g_face[14][gi];
        int bi = zbucket(zmx);
        int pos = atomicAdd(&offs[bi], 1);
        int go = b * NF + pos;
        g_q0[go] = make_float4(g_face[0][gi], g_face[1][gi], g_face[2][gi], g_face[3][gi]);
        g_q1[go] = make_float4(g_face[4][gi], g_face[5][gi], g_face[6][gi], zmx);
        g_q2[go] = make_float4(g_face[7][gi], g_face[8][gi], g_face[9][gi], __int_as_float(i));
        g_qb[go] = make_float4(g_face[10][gi], g_face[11][gi], g_face[12][gi], g_face[13][gi]);
        unsigned ub = __float_as_uint(zmx);
        unsigned enc = (ub & 0x80000000u) ? ~ub : (ub | 0x80000000u);
        atomicMax(&schunkmax[pos / TF], enc);
    }
    __syncthreads();

    if (tid == 0) {
        float bound = -3e30f;
        for (int c = NCHUNK - 1; c >= 0; c--) {
            unsigned enc = schunkmax[c];
            unsigned ub = (enc & 0x80000000u) ? (enc & 0x7FFFFFFFu) : ~enc;
            float zm = __uint_as_float(ub);
            bound = fmaxf(bound, zm);
            g_chunkbound[b * NCHUNK + c] = bound;
        }
    }
}

// ---- raster: 16x8 pixel tile per block, 128 threads, 1 pixel per thread ----
__global__ void __launch_bounds__(NTHR) raster(const float* __restrict__ verts,
                                               const int* __restrict__ faces,
                                               float* __restrict__ out) {
    __shared__ float4 sQ0[TF], sQ1[TF], sQ2[TF];
    __shared__ int scount;
    __shared__ float swred[4];
    __shared__ float sblockmin;

    const int b = blockIdx.z;
    const int tid = threadIdx.x;
    const int tx = tid & 15;
    const int ty = tid >> 4;

    const int pxi = blockIdx.x * 16 + tx;
    const int pyi = blockIdx.y * 8 + ty;

    const float px = ((float)pxi + 0.5f) / 256.0f * 2.0f - 1.0f;
    const float py = ((float)pyi + 0.5f) / 256.0f * 2.0f - 1.0f;

    const float eps = 1e-4f;
    const float blk_xmin = (blockIdx.x * 16 + 0.5f)  / 256.0f * 2.0f - 1.0f - eps;
    const float blk_xmax = (blockIdx.x * 16 + 15.5f) / 256.0f * 2.0f - 1.0f + eps;
    const float blk_ymin = (blockIdx.y * 8 + 0.5f)   / 256.0f * 2.0f - 1.0f - eps;
    const float blk_ymax = (blockIdx.y * 8 + 7.5f)   / 256.0f * 2.0f - 1.0f + eps;

    float bz = -1.0f;
    int bf = -1;
    float bw0 = 0.0f, bw1 = 0.0f, bw2 = 0.0f;

    // previous-chunk block-min bz, usable for compaction culling (starts at -1)
    float blockmin_prev = -1.0f;

    for (int base = 0; base < NF; base += TF) {
        if (tid == 0) scount = 0;
        __syncthreads();
        if (base > 0) {
            blockmin_prev = sblockmin;
            if (g_chunkbound[b * NCHUNK + base / TF] < blockmin_prev) break;
        }

        // compaction: bbox + exact-conservative edge test + zmax-vs-blockmin
#pragma unroll
        for (int k = 0; k < TF / NTHR; k++) {
            int r = b * NF + base + tid + k * NTHR;
            float4 qb = g_qb[r];
            if (qb.y >= blk_xmin && qb.x <= blk_xmax && qb.w >= blk_ymin && qb.z <= blk_ymax) {
                float4 q1 = g_q1[r];
                if (q1.w < blockmin_prev) continue;  // can't beat/tie any pixel in block
                float4 q0 = g_q0[r];
                // affine coefficients of w0, w1 in (x, y):
                const float inv = q1.z;
                float a0 = q0.x * inv, b0 = q0.y * inv;
                float a1 = q0.z * inv, b1 = q0.w * inv;
                float c0 = -(a0 * q1.x + b0 * q1.y);
                float c1 = -(a1 * q1.x + b1 * q1.y);
                // max of each w over tile rectangle (affine -> corner extremes)
                float maxw0 = fmaxf(a0 * blk_xmin, a0 * blk_xmax)
                            + fmaxf(b0 * blk_ymin, b0 * blk_ymax) + c0;
                float maxw1 = fmaxf(a1 * blk_xmin, a1 * blk_xmax)
                            + fmaxf(b1 * blk_ymin, b1 * blk_ymax) + c1;
                float a2 = -(a0 + a1), b2 = -(b0 + b1), c2 = 1.0f - c0 - c1;
                float maxw2 = fmaxf(a2 * blk_xmin, a2 * blk_xmax)
                            + fmaxf(b2 * blk_ymin, b2 * blk_ymax) + c2;
                const float m = -1e-5f;  // safety margin vs FMA-ordering noise
                if (maxw0 < m || maxw1 < m || maxw2 < m) continue;
                int slot = atomicAdd(&scount, 1);
                sQ0[slot] = q0;
                sQ1[slot] = q1;
                sQ2[slot] = g_q2[r];
            }
        }
        __syncthreads();

        // warp-uniform chunk skip: this warp already beats everything left in chunk?
        float warpmin = bz;
#pragma unroll
        for (int s = 16; s > 0; s >>= 1)
            warpmin = fminf(warpmin, __shfl_xor_sync(0xffffffffu, warpmin, s));
        bool warp_skip = (g_chunkbound[b * NCHUNK + base / TF] < warpmin);

        const int cnt = scount;
        if (!warp_skip) {
            for (int j = 0; j < cnt; j++) {
                float4 q1 = sQ1[j];
                if (q1.w < bz) continue;
                float4 q0 = sQ0[j];
                float4 q2 = sQ2[j];
                const float inv = q1.z;
                const float dx = px - q1.x;
                const float dy = py - q1.y;
                float w0 = (q0.x * dx + q0.y * dy) * inv;
                float w1 = (q0.z * dx + q0.w * dy) * inv;
                float w2 = 1.0f - w0 - w1;
                if (w0 >= 0.0f && w1 >= 0.0f && w2 >= 0.0f) {
                    float z = w0 * q2.x + w1 * q2.y + w2 * q2.z;
                    int f2 = __float_as_int(q2.w);
                    if (z > bz || (z == bz && bf >= 0 && f2 < bf)) {
                        bz = z; bf = f2;
                        bw0 = w0; bw1 = w1; bw2 = w2;
                    }
                }
            }
        }

        // block-wide min bz for next chunk
        float v = bz;
#pragma unroll
        for (int s = 16; s > 0; s >>= 1)
            v = fminf(v, __shfl_xor_sync(0xffffffffu, v, s));
        if ((tid & 31) == 0) swred[tid >> 5] = v;
        __syncthreads();
        if (tid == 0)
            sblockmin = fminf(fminf(swred[0], swred[1]), fminf(swred[2], swred[3]));
        __syncthreads();
    }

    // ---- shading + store ----
    float* rend = out;
    float* al   = out + (size_t)NB * 6 * PP;
    float* fo   = al  + (size_t)NB * PP;
    float* zo   = fo  + (size_t)NB * PP;

    const int pix = pyi * IW + pxi;
    const float alpha = (bf >= 0) ? 1.0f : 0.0f;
    const int sf = (bf >= 0) ? bf : 0;
    const int i0 = faces[sf * 3 + 0];
    const int i1 = faces[sf * 3 + 1];
    const int i2 = faces[sf * 3 + 2];

    const float* c0 = &g_vcol[((size_t)b * NV + i0) * 3];
    const float* c1 = &g_vcol[((size_t)b * NV + i1) * 3];
    const float* c2 = &g_vcol[((size_t)b * NV + i2) * 3];
    const float* v0 = verts + ((size_t)b * NV + i0) * 3;
    const float* v1 = verts + ((size_t)b * NV + i1) * 3;
    const float* v2 = verts + ((size_t)b * NV + i2) * 3;

    float ch[6];
#pragma unroll
    for (int c = 0; c < 3; c++)
        ch[c] = c0[c] * bw0 + c1[c] * bw1 + c2[c] * bw2;
#pragma unroll
    for (int c = 0; c < 3; c++)
        ch[3 + c] = v0[c] * bw0 + v1[c] * bw1 + v2[c] * bw2;

#pragma unroll
    for (int c = 0; c < 6; c++)
        rend[((size_t)b * 6 + c) * PP + pix] = ch[c] * alpha;
    al[(size_t)b * PP + pix] = alpha;
    fo[(size_t)b * PP + pix] = (float)bf;
    zo[(size_t)b * PP + pix] = bz;
}

extern "C" void kernel_launch(void* const* d_in, const int* in_sizes, int n_in,
                              void* d_out, int out_size) {
    const float* vertices = (const float*)d_in[0];
    const float* tverts   = (const float*)d_in[1];
    const float* tex      = (const float*)d_in[2];
    const float* uv       = (const float*)d_in[3];
    const int*   faces    = (const int*)d_in[4];
    float* out = (float*)d_out;

    prep<<<(NB * NV + 255) / 256, 256>>>(tverts, faces, tex, uv);
    sortpack<<<NB, 1024>>>();
    dim3 grid(IW / 16, IH / 8, NB);
    raster<<<grid, NTHR>>>(vertices, faces, out);
}

// round 6
// speedup vs baseline: 3.5810x; 1.0220x over previous
#include <cuda_runtime.h>
#include <math.h>

// Problem constants
#define NB 2
#define NV 5023
#define NF 2048
#define IH 256
#define IW 256
#define PP (IH * IW)
#define TF 256               // faces per smem chunk
#define NCHUNK (NF / TF)     // 8
#define NTHR 128
#define SORT_THR 1024
#define FPB (NF / SORT_THR)  // 2 faces per sort thread
#define VCOL_BLKS ((NB * NV + SORT_THR - 1) / SORT_THR)  // 10

// Packed, approx-zmax-descending per-face records
__device__ float4 g_q0[NB * NF];  // A0,B0,A1,B1
__device__ float4 g_q1[NB * NF];  // x2,y2,inv,zmax
__device__ float4 g_q2[NB * NF];  // z0,z1,z2,face_id(bits)
__device__ float4 g_qb[NB * NF];  // xmin,xmax,ymin,ymax
__device__ float g_chunkbound[NB * NCHUNK];
__device__ float g_vcol[NB * NV * 3];

__device__ __forceinline__ unsigned encf(float x) {
    unsigned u = __float_as_uint(x);
    return (u & 0x80000000u) ? ~u : (u | 0x80000000u);
}
__device__ __forceinline__ float decf(unsigned e) {
    unsigned u = (e & 0x80000000u) ? (e & 0x7FFFFFFFu) : ~e;
    return __uint_as_float(u);
}
__device__ __forceinline__ int zbucket(float zmx) {
    int bi = (int)((1.0f - zmx) * 127.5f);
    return min(max(bi, 0), 255);
}

// ---- fused pre: blocks [0,NB) = face setup + counting sort + pack;
//                 blocks [NB, NB+VCOL_BLKS) = per-vertex texture sampling ----
__global__ void __launch_bounds__(SORT_THR) pre(const float* __restrict__ tv,
                                                const int* __restrict__ faces,
                                                const float* __restrict__ tex,
                                                const float* __restrict__ uv) {
    const int tid = threadIdx.x;

    if (blockIdx.x >= NB) {
        // ---- vcol part ----
        int idx = (blockIdx.x - NB) * SORT_THR + tid;
        if (idx >= NB * NV) return;
        int b = idx / NV, v = idx % NV;
        float u = uv[v * 2 + 0] * 255.0f;
        float vv = uv[v * 2 + 1] * 255.0f;
        float u0f = floorf(u);
        float v0f = floorf(vv);
        u0f = fminf(fmaxf(u0f, 0.0f), 254.0f);
        v0f = fminf(fmaxf(v0f, 0.0f), 254.0f);
        int u0 = (int)u0f;
        int v0 = (int)v0f;
        float fu = u - u0f;
        float fv = vv - v0f;
        const float* t = tex + (size_t)b * 256 * 256 * 3;
        const float* r0 = t + ((size_t)v0 * 256 + u0) * 3;
        const float* r1 = t + ((size_t)(v0 + 1) * 256 + u0) * 3;
#pragma unroll
        for (int c = 0; c < 3; c++) {
            float c00 = r0[c];
            float c01 = r0[3 + c];
            float c10 = r1[c];
            float c11 = r1[3 + c];
            float top = c00 * (1.0f - fu) + c01 * fu;
            float bot = c10 * (1.0f - fu) + c11 * fu;
            g_vcol[idx * 3 + c] = top * (1.0f - fv) + bot * fv;
        }
        return;
    }

    // ---- face setup + counting sort (one block per batch) ----
    __shared__ int hist[256];
    __shared__ int offs[256];
    __shared__ unsigned chunkmaxEnc[NCHUNK];
    const int b = blockIdx.x;

    // per-thread face records in registers
    float4 rq0[FPB], rq1[FPB], rq2[FPB], rqb[FPB];
    int rbkt[FPB];

    if (tid < 256) hist[tid] = 0;
    if (tid < NCHUNK) chunkmaxEnc[tid] = 0u;

#pragma unroll
    for (int k = 0; k < FPB; k++) {
        int f = tid + k * SORT_THR;
        int i0 = faces[f * 3 + 0];
        int i1 = faces[f * 3 + 1];
        int i2 = faces[f * 3 + 2];
        const float* p0 = tv + ((size_t)b * NV + i0) * 3;
        const float* p1 = tv + ((size_t)b * NV + i1) * 3;
        const float* p2 = tv + ((size_t)b * NV + i2) * 3;
        float x0 = p0[0], y0 = p0[1], z0 = p0[2];
        float x1 = p1[0], y1 = p1[1], z1 = p1[2];
        float x2 = p2[0], y2 = p2[1], z2 = p2[2];

        float denom = (y1 - y2) * (x0 - x2) + (x2 - x1) * (y0 - y2);
        bool valid = fabsf(denom) > 1e-8f;
        float inv = valid ? (1.0f / denom) : 0.0f;

        float xmn = fminf(x0, fminf(x1, x2));
        float xmx = fmaxf(x0, fmaxf(x1, x2));
        float ymn = fminf(y0, fminf(y1, y2));
        float ymx = fmaxf(y0, fmaxf(y1, y2));
        float zmx = fmaxf(z0, fmaxf(z1, z2));
        if (!valid) { xmn = 2e30f; xmx = -2e30f; ymn = 2e30f; ymx = -2e30f; zmx = -3e30f; }

        rq0[k] = make_float4(y1 - y2, x2 - x1, y2 - y0, x0 - x2);
        rq1[k] = make_float4(x2, y2, inv, zmx);
        rq2[k] = make_float4(z0, z1, z2, __int_as_float(f));
        rqb[k] = make_float4(xmn, xmx, ymn, ymx);
        rbkt[k] = zbucket(zmx);
    }
    __syncthreads();

#pragma unroll
    for (int k = 0; k < FPB; k++) atomicAdd(&hist[rbkt[k]], 1);
    __syncthreads();

    // inclusive scan over 256 buckets
    if (tid < 256) offs[tid] = hist[tid];
    __syncthreads();
#pragma unroll
    for (int s = 1; s < 256; s <<= 1) {
        int v = 0;
        if (tid < 256 && tid >= s) v = offs[tid - s];
        __syncthreads();
        if (tid < 256) offs[tid] += v;
        __syncthreads();
    }
    int myExcl = 0;
    if (tid < 256) myExcl = offs[tid] - hist[tid];
    __syncthreads();
    if (tid < 256) offs[tid] = myExcl;
    __syncthreads();

    // scatter from registers
#pragma unroll
    for (int k = 0; k < FPB; k++) {
        int pos = atomicAdd(&offs[rbkt[k]], 1);
        int go = b * NF + pos;
        g_q0[go] = rq0[k];
        g_q1[go] = rq1[k];
        g_q2[go] = rq2[k];
        g_qb[go] = rqb[k];
        atomicMax(&chunkmaxEnc[pos / TF], encf(rq1[k].w));
    }
    __syncthreads();

    if (tid == 0) {
        float bound = -3e30f;
        for (int c = NCHUNK - 1; c >= 0; c--) {
            bound = fmaxf(bound, decf(chunkmaxEnc[c]));
            g_chunkbound[b * NCHUNK + c] = bound;
        }
    }
}

// ---- raster: 16x8 pixel tile per block, 128 threads, 1 pixel per thread ----
__global__ void __launch_bounds__(NTHR) raster(const float* __restrict__ verts,
                                               const int* __restrict__ faces,
                                               float* __restrict__ out) {
    __shared__ float4 sQ0[TF], sQ1[TF], sQ2[TF];
    __shared__ int scount;
    __shared__ unsigned sminEnc[2];  // parity double-buffered block-min bz

    const int b = blockIdx.z;
    const int tid = threadIdx.x;
    const int tx = tid & 15;
    const int ty = tid >> 4;

    const int pxi = blockIdx.x * 16 + tx;
    const int pyi = blockIdx.y * 8 + ty;

    const float px = ((float)pxi + 0.5f) / 256.0f * 2.0f - 1.0f;
    const float py = ((float)pyi + 0.5f) / 256.0f * 2.0f - 1.0f;

    const float eps = 1e-4f;
    const float blk_xmin = (blockIdx.x * 16 + 0.5f)  / 256.0f * 2.0f - 1.0f - eps;
    const float blk_xmax = (blockIdx.x * 16 + 15.5f) / 256.0f * 2.0f - 1.0f + eps;
    const float blk_ymin = (blockIdx.y * 8 + 0.5f)   / 256.0f * 2.0f - 1.0f - eps;
    const float blk_ymax = (blockIdx.y * 8 + 7.5f)   / 256.0f * 2.0f - 1.0f + eps;

    float bz = -1.0f;
    int bf = -1;
    float bw0 = 0.0f, bw1 = 0.0f, bw2 = 0.0f;
    float warpmin = -1.0f;       // carried across chunks (post-loop reduction)
    float blockmin_prev = -1.0f;

    for (int c = 0; c < NCHUNK; c++) {
        const int base = c * TF;
        if (tid == 0) scount = 0;
        if (tid == 32) sminEnc[c & 1] = 0xFFFFFFFFu;  // reset this chunk's slot
        __syncthreads();  // publishes prev chunk's atomicMins + resets

        const float cbound = g_chunkbound[b * NCHUNK + c];
        if (c > 0) {
            blockmin_prev = decf(sminEnc[(c - 1) & 1]);
            if (cbound < blockmin_prev) break;
        }

        // compaction: bbox + zmax-vs-blockmin + exact-conservative edge test
#pragma unroll
        for (int k = 0; k < TF / NTHR; k++) {
            int r = b * NF + base + tid + k * NTHR;
            float4 qb = g_qb[r];
            if (qb.y >= blk_xmin && qb.x <= blk_xmax && qb.w >= blk_ymin && qb.z <= blk_ymax) {
                float4 q1 = g_q1[r];
                if (q1.w < blockmin_prev) continue;
                float4 q0 = g_q0[r];
                const float inv = q1.z;
                float a0 = q0.x * inv, b0 = q0.y * inv;
                float a1 = q0.z * inv, b1 = q0.w * inv;
                float c0 = -(a0 * q1.x + b0 * q1.y);
                float c1 = -(a1 * q1.x + b1 * q1.y);
                float maxw0 = fmaxf(a0 * blk_xmin, a0 * blk_xmax)
                            + fmaxf(b0 * blk_ymin, b0 * blk_ymax) + c0;
                float maxw1 = fmaxf(a1 * blk_xmin, a1 * blk_xmax)
                            + fmaxf(b1 * blk_ymin, b1 * blk_ymax) + c1;
                float a2 = -(a0 + a1), b2 = -(b0 + b1), c2 = 1.0f - c0 - c1;
                float maxw2 = fmaxf(a2 * blk_xmin, a2 * blk_xmax)
                            + fmaxf(b2 * blk_ymin, b2 * blk_ymax) + c2;
                const float m = -1e-5f;
                if (maxw0 < m || maxw1 < m || maxw2 < m) continue;
                int slot = atomicAdd(&scount, 1);
                sQ0[slot] = q0;
                sQ1[slot] = q1;
                sQ2[slot] = g_q2[r];
            }
        }
        __syncthreads();

        const int cnt = scount;
        if (cbound >= warpmin) {  // warp-uniform skip otherwise
            for (int j = 0; j < cnt; j++) {
                float4 q1 = sQ1[j];
                if (q1.w < bz) continue;
                float4 q0 = sQ0[j];
                float4 q2 = sQ2[j];
                const float inv = q1.z;
                const float dx = px - q1.x;
                const float dy = py - q1.y;
                float w0 = (q0.x * dx + q0.y * dy) * inv;
                float w1 = (q0.z * dx + q0.w * dy) * inv;
                float w2 = 1.0f - w0 - w1;
                if (w0 >= 0.0f && w1 >= 0.0f && w2 >= 0.0f) {
                    float z = w0 * q2.x + w1 * q2.y + w2 * q2.z;
                    int f2 = __float_as_int(q2.w);
                    if (z > bz || (z == bz && bf >= 0 && f2 < bf)) {
                        bz = z; bf = f2;
                        bw0 = w0; bw1 = w1; bw2 = w2;
                    }
                }
            }
        }

        // warp min of bz -> shared atomicMin (published at next chunk's sync)
        float v = bz;
#pragma unroll
        for (int s = 16; s > 0; s >>= 1)
            v = fminf(v, __shfl_xor_sync(0xffffffffu, v, s));
        warpmin = v;
        if ((tid & 31) == 0) atomicMin(&sminEnc[c & 1], encf(v));
    }

    // ---- shading + store ----
    float* rend = out;
    float* al   = out + (size_t)NB * 6 * PP;
    float* fo   = al  + (size_t)NB * PP;
    float* zo   = fo  + (size_t)NB * PP;

    const int pix = pyi * IW + pxi;
    const float alpha = (bf >= 0) ? 1.0f : 0.0f;
    const int sf = (bf >= 0) ? bf : 0;
    const int i0 = faces[sf * 3 + 0];
    const int i1 = faces[sf * 3 + 1];
    const int i2 = faces[sf * 3 + 2];

    const float* c0 = &g_vcol[((size_t)b * NV + i0) * 3];
    const float* c1 = &g_vcol[((size_t)b * NV + i1) * 3];
    const float* c2 = &g_vcol[((size_t)b * NV + i2) * 3];
    const float* v0 = verts + ((size_t)b * NV + i0) * 3;
    const float* v1 = verts + ((size_t)b * NV + i1) * 3;
    const float* v2 = verts + ((size_t)b * NV + i2) * 3;

    float ch[6];
#pragma unroll
    for (int c = 0; c < 3; c++)
        ch[c] = c0[c] * bw0 + c1[c] * bw1 + c2[c] * bw2;
#pragma unroll
    for (int c = 0; c < 3; c++)
        ch[3 + c] = v0[c] * bw0 + v1[c] * bw1 + v2[c] * bw2;

#pragma unroll
    for (int c = 0; c < 6; c++)
        rend[((size_t)b * 6 + c) * PP + pix] = ch[c] * alpha;
    al[(size_t)b * PP + pix] = alpha;
    fo[(size_t)b * PP + pix] = (float)bf;
    zo[(size_t)b * PP + pix] = bz;
}

extern "C" void kernel_launch(void* const* d_in, const int* in_sizes, int n_in,
                              void* d_out, int out_size) {
    const float* vertices = (const float*)d_in[0];
    const float* tverts   = (const float*)d_in[1];
    const float* tex      = (const float*)d_in[2];
    const float* uv       = (const float*)d_in[3];
    const int*   faces    = (const int*)d_in[4];
    float* out = (float*)d_out;

    pre<<<NB + VCOL_BLKS, SORT_THR>>>(tverts, faces, tex, uv);
    dim3 grid(IW / 16, IH / 8, NB);
    raster<<<grid, NTHR>>>(vertices, faces, out);
}

// round 7
// speedup vs baseline: 3.8366x; 1.0714x over previous
#include <cuda_runtime.h>
#include <math.h>

// Problem constants
#define NB 2
#define NV 5023
#define NF 2048
#define IH 256
#define IW 256
#define PP (IH * IW)
#define TF 256               // faces per smem chunk
#define NCHUNK (NF / TF)     // 8
#define SPLIT 2              // face-partition blocks per tile
#define NTHR 128
#define SORT_THR 1024
#define FPB (NF / SORT_THR)
#define VCOL_BLKS ((NB * NV + SORT_THR - 1) / SORT_THR)     // 10
#define ZINIT_BLKS ((NB * PP + SORT_THR * 8 - 1) / (SORT_THR * 8))  // 16

// Packed, approx-zmax-descending per-face records
__device__ float4 g_q0[NB * NF];  // A0,B0,A1,B1
__device__ float4 g_q1[NB * NF];  // x2,y2,inv,zmax
__device__ float4 g_q2[NB * NF];  // z0,z1,z2,face_id(bits)
__device__ float4 g_qb[NB * NF];  // xmin,xmax,ymin,ymax
__device__ float g_chunkbound[NB * NCHUNK];   // per-parity suffix max
__device__ float g_vcol[NB * NV * 3];
__device__ unsigned long long g_zfid[NB * PP]; // (enc(z)<<32)|~fid

__device__ __forceinline__ unsigned encf(float x) {
    unsigned u = __float_as_uint(x);
    return (u & 0x80000000u) ? ~u : (u | 0x80000000u);
}
__device__ __forceinline__ float decf(unsigned e) {
    unsigned u = (e & 0x80000000u) ? (e & 0x7FFFFFFFu) : ~e;
    return __uint_as_float(u);
}
__device__ __forceinline__ int zbucket(float zmx) {
    int bi = (int)((1.0f - zmx) * 127.5f);
    return min(max(bi, 0), 255);
}

// ---- fused pre: blocks [0,NB) face setup+sort+pack; [NB,NB+VCOL) vcol; rest zfid init ----
__global__ void __launch_bounds__(SORT_THR) pre(const float* __restrict__ tv,
                                                const int* __restrict__ faces,
                                                const float* __restrict__ tex,
                                                const float* __restrict__ uv) {
    const int tid = threadIdx.x;

    if (blockIdx.x >= NB + VCOL_BLKS) {
        // ---- zfid init ----
        const unsigned long long initv = ((unsigned long long)encf(-1.0f) << 32) | 0ull;
        int base = (blockIdx.x - NB - VCOL_BLKS) * SORT_THR * 8 + tid;
#pragma unroll
        for (int k = 0; k < 8; k++) {
            int i = base + k * SORT_THR;
            if (i < NB * PP) g_zfid[i] = initv;
        }
        return;
    }

    if (blockIdx.x >= NB) {
        // ---- vcol part ----
        int idx = (blockIdx.x - NB) * SORT_THR + tid;
        if (idx >= NB * NV) return;
        int b = idx / NV, v = idx % NV;
        float u = uv[v * 2 + 0] * 255.0f;
        float vv = uv[v * 2 + 1] * 255.0f;
        float u0f = floorf(u);
        float v0f = floorf(vv);
        u0f = fminf(fmaxf(u0f, 0.0f), 254.0f);
        v0f = fminf(fmaxf(v0f, 0.0f), 254.0f);
        int u0 = (int)u0f;
        int v0 = (int)v0f;
        float fu = u - u0f;
        float fv = vv - v0f;
        const float* t = tex + (size_t)b * 256 * 256 * 3;
        const float* r0 = t + ((size_t)v0 * 256 + u0) * 3;
        const float* r1 = t + ((size_t)(v0 + 1) * 256 + u0) * 3;
#pragma unroll
        for (int c = 0; c < 3; c++) {
            float c00 = r0[c];
            float c01 = r0[3 + c];
            float c10 = r1[c];
            float c11 = r1[3 + c];
            float top = c00 * (1.0f - fu) + c01 * fu;
            float bot = c10 * (1.0f - fu) + c11 * fu;
            g_vcol[idx * 3 + c] = top * (1.0f - fv) + bot * fv;
        }
        return;
    }

    // ---- face setup + counting sort (one block per batch) ----
    __shared__ int hist[256];
    __shared__ int offs[256];
    __shared__ unsigned chunkmaxEnc[NCHUNK];
    const int b = blockIdx.x;

    float4 rq0[FPB], rq1[FPB], rq2[FPB], rqb[FPB];
    int rbkt[FPB];

    if (tid < 256) hist[tid] = 0;
    if (tid < NCHUNK) chunkmaxEnc[tid] = 0u;

#pragma unroll
    for (int k = 0; k < FPB; k++) {
        int f = tid + k * SORT_THR;
        int i0 = faces[f * 3 + 0];
        int i1 = faces[f * 3 + 1];
        int i2 = faces[f * 3 + 2];
        const float* p0 = tv + ((size_t)b * NV + i0) * 3;
        const float* p1 = tv + ((size_t)b * NV + i1) * 3;
        const float* p2 = tv + ((size_t)b * NV + i2) * 3;
        float x0 = p0[0], y0 = p0[1], z0 = p0[2];
        float x1 = p1[0], y1 = p1[1], z1 = p1[2];
        float x2 = p2[0], y2 = p2[1], z2 = p2[2];

        float denom = (y1 - y2) * (x0 - x2) + (x2 - x1) * (y0 - y2);
        bool valid = fabsf(denom) > 1e-8f;
        float inv = valid ? (1.0f / denom) : 0.0f;

        float xmn = fminf(x0, fminf(x1, x2));
        float xmx = fmaxf(x0, fmaxf(x1, x2));
        float ymn = fminf(y0, fminf(y1, y2));
        float ymx = fmaxf(y0, fmaxf(y1, y2));
        float zmx = fmaxf(z0, fmaxf(z1, z2));
        if (!valid) { xmn = 2e30f; xmx = -2e30f; ymn = 2e30f; ymx = -2e30f; zmx = -3e30f; }

        rq0[k] = make_float4(y1 - y2, x2 - x1, y2 - y0, x0 - x2);
        rq1[k] = make_float4(x2, y2, inv, zmx);
        rq2[k] = make_float4(z0, z1, z2, __int_as_float(f));
        rqb[k] = make_float4(xmn, xmx, ymn, ymx);
        rbkt[k] = zbucket(zmx);
    }
    __syncthreads();

#pragma unroll
    for (int k = 0; k < FPB; k++) atomicAdd(&hist[rbkt[k]], 1);
    __syncthreads();

    if (tid < 256) offs[tid] = hist[tid];
    __syncthreads();
#pragma unroll
    for (int s = 1; s < 256; s <<= 1) {
        int v = 0;
        if (tid < 256 && tid >= s) v = offs[tid - s];
        __syncthreads();
        if (tid < 256) offs[tid] += v;
        __syncthreads();
    }
    int myExcl = 0;
    if (tid < 256) myExcl = offs[tid] - hist[tid];
    __syncthreads();
    if (tid < 256) offs[tid] = myExcl;
    __syncthreads();

#pragma unroll
    for (int k = 0; k < FPB; k++) {
        int pos = atomicAdd(&offs[rbkt[k]], 1);
        int go = b * NF + pos;
        g_q0[go] = rq0[k];
        g_q1[go] = rq1[k];
        g_q2[go] = rq2[k];
        g_qb[go] = rqb[k];
        atomicMax(&chunkmaxEnc[pos / TF], encf(rq1[k].w));
    }
    __syncthreads();

    if (tid == 0) {
        // per-parity suffix max: bound[c] >= zmax of every face in chunks {c, c+SPLIT, ...}
#pragma unroll
        for (int s = 0; s < SPLIT; s++) {
            float bound = -3e30f;
            for (int c = NCHUNK - SPLIT + s; c >= 0; c -= SPLIT) {
                bound = fmaxf(bound, decf(chunkmaxEnc[c]));
                g_chunkbound[b * NCHUNK + c] = bound;
            }
        }
    }
}

// ---- raster: 16x8 tile per block; SPLIT blocks per tile over interleaved chunks ----
__global__ void __launch_bounds__(NTHR) raster() {
    __shared__ float4 sQ0[TF], sQ1[TF], sQ2[TF];
    __shared__ int scount;
    __shared__ unsigned sminEnc[2];

    const int b = blockIdx.z / SPLIT;
    const int sp = blockIdx.z % SPLIT;
    const int tid = threadIdx.x;
    const int tx = tid & 15;
    const int ty = tid >> 4;

    const int pxi = blockIdx.x * 16 + tx;
    const int pyi = blockIdx.y * 8 + ty;
    const int pix = pyi * IW + pxi;

    const float px = ((float)pxi + 0.5f) / 256.0f * 2.0f - 1.0f;
    const float py = ((float)pyi + 0.5f) / 256.0f * 2.0f - 1.0f;

    const float eps = 1e-4f;
    const float blk_xmin = (blockIdx.x * 16 + 0.5f)  / 256.0f * 2.0f - 1.0f - eps;
    const float blk_xmax = (blockIdx.x * 16 + 15.5f) / 256.0f * 2.0f - 1.0f + eps;
    const float blk_ymin = (blockIdx.y * 8 + 0.5f)   / 256.0f * 2.0f - 1.0f - eps;
    const float blk_ymax = (blockIdx.y * 8 + 7.5f)   / 256.0f * 2.0f - 1.0f + eps;

    float bz = -1.0f;
    int bf = -1;
    float warpmin = -1.0f;
    float blockmin_prev = -1.0f;
    int it = 0;

    for (int c = sp; c < NCHUNK; c += SPLIT, it++) {
        const int base = c * TF;
        if (tid == 0) scount = 0;
        if (tid == 32) sminEnc[it & 1] = 0xFFFFFFFFu;
        __syncthreads();

        const float cbound = g_chunkbound[b * NCHUNK + c];
        if (it > 0) {
            blockmin_prev = decf(sminEnc[(it - 1) & 1]);
            if (cbound < blockmin_prev) break;
        }

#pragma unroll
        for (int k = 0; k < TF / NTHR; k++) {
            int r = b * NF + base + tid + k * NTHR;
            float4 qb = g_qb[r];
            if (qb.y >= blk_xmin && qb.x <= blk_xmax && qb.w >= blk_ymin && qb.z <= blk_ymax) {
                float4 q1 = g_q1[r];
                if (q1.w < blockmin_prev) continue;
                float4 q0 = g_q0[r];
                const float inv = q1.z;
                float a0 = q0.x * inv, b0 = q0.y * inv;
                float a1 = q0.z * inv, b1 = q0.w * inv;
                float c0 = -(a0 * q1.x + b0 * q1.y);
                float c1 = -(a1 * q1.x + b1 * q1.y);
                float maxw0 = fmaxf(a0 * blk_xmin, a0 * blk_xmax)
                            + fmaxf(b0 * blk_ymin, b0 * blk_ymax) + c0;
                float maxw1 = fmaxf(a1 * blk_xmin, a1 * blk_xmax)
                            + fmaxf(b1 * blk_ymin, b1 * blk_ymax) + c1;
                float a2 = -(a0 + a1), b2 = -(b0 + b1), c2 = 1.0f - c0 - c1;
                float maxw2 = fmaxf(a2 * blk_xmin, a2 * blk_xmax)
                            + fmaxf(b2 * blk_ymin, b2 * blk_ymax) + c2;
                const float m = -1e-5f;
                if (maxw0 < m || maxw1 < m || maxw2 < m) continue;
                int slot = atomicAdd(&scount, 1);
                sQ0[slot] = q0;
                sQ1[slot] = q1;
                sQ2[slot] = g_q2[r];
            }
        }
        __syncthreads();

        const int cnt = scount;
        if (cbound >= warpmin) {
            for (int j = 0; j < cnt; j++) {
                float4 q1 = sQ1[j];
                if (q1.w < bz) continue;
                float4 q0 = sQ0[j];
                float4 q2 = sQ2[j];
                const float inv = q1.z;
                const float dx = px - q1.x;
                const float dy = py - q1.y;
                float w0 = (q0.x * dx + q0.y * dy) * inv;
                float w1 = (q0.z * dx + q0.w * dy) * inv;
                float w2 = 1.0f - w0 - w1;
                if (w0 >= 0.0f && w1 >= 0.0f && w2 >= 0.0f) {
                    float z = w0 * q2.x + w1 * q2.y + w2 * q2.z;
                    int f2 = __float_as_int(q2.w);
                    if (z > bz || (z == bz && bf >= 0 && f2 < bf)) {
                        bz = z; bf = f2;
                    }
                }
            }
        }

        float v = bz;
#pragma unroll
        for (int s = 16; s > 0; s >>= 1)
            v = fminf(v, __shfl_xor_sync(0xffffffffu, v, s));
        warpmin = v;
        if ((tid & 31) == 0) atomicMin(&sminEnc[it & 1], encf(v));
    }

    // merge: lexicographic (z, -fid) max — exact scan/argmax semantics
    if (bf >= 0) {
        unsigned long long v = ((unsigned long long)encf(bz) << 32)
                             | (unsigned long long)(~(unsigned)bf);
        atomicMax(&g_zfid[(size_t)b * PP + pix], v);
    }
}

// ---- shade: decode winner, recompute bary, gather attrs, write all outputs ----
__global__ void shade(const float* __restrict__ verts,
                      const float* __restrict__ tverts,
                      const int* __restrict__ faces,
                      float* __restrict__ out) {
    int idx = blockIdx.x * blockDim.x + threadIdx.x;
    if (idx >= NB * PP) return;
    const int b = idx / PP;
    const int pix = idx % PP;
    const int pxi = pix & 255;
    const int pyi = pix >> 8;
    const float px = ((float)pxi + 0.5f) / 256.0f * 2.0f - 1.0f;
    const float py = ((float)pyi + 0.5f) / 256.0f * 2.0f - 1.0f;

    unsigned long long v = g_zfid[idx];
    float bz = decf((unsigned)(v >> 32));
    int bf = (int)(~(unsigned)(v & 0xFFFFFFFFu));

    float bw0 = 0.0f, bw1 = 0.0f, bw2 = 0.0f;
    const float alpha = (bf >= 0) ? 1.0f : 0.0f;
    const int sf = (bf >= 0) ? bf : 0;
    const int i0 = faces[sf * 3 + 0];
    const int i1 = faces[sf * 3 + 1];
    const int i2 = faces[sf * 3 + 2];

    if (bf >= 0) {
        const float* p0 = tverts + ((size_t)b * NV + i0) * 3;
        const float* p1 = tverts + ((size_t)b * NV + i1) * 3;
        const float* p2 = tverts + ((size_t)b * NV + i2) * 3;
        float x0 = p0[0], y0 = p0[1];
        float x1 = p1[0], y1 = p1[1];
        float x2 = p2[0], y2 = p2[1];
        float denom = (y1 - y2) * (x0 - x2) + (x2 - x1) * (y0 - y2);
        float inv = (fabsf(denom) > 1e-8f) ? (1.0f / denom) : 0.0f;
        float dx = px - x2;
        float dy = py - y2;
        bw0 = ((y1 - y2) * dx + (x2 - x1) * dy) * inv;
        bw1 = ((y2 - y0) * dx + (x0 - x2) * dy) * inv;
        bw2 = 1.0f - bw0 - bw1;
    }

    const float* c0 = &g_vcol[((size_t)b * NV + i0) * 3];
    const float* c1 = &g_vcol[((size_t)b * NV + i1) * 3];
    const float* c2 = &g_vcol[((size_t)b * NV + i2) * 3];
    const float* v0 = verts + ((size_t)b * NV + i0) * 3;
    const float* v1 = verts + ((size_t)b * NV + i1) * 3;
    const float* v2 = verts + ((size_t)b * NV + i2) * 3;

    float ch[6];
#pragma unroll
    for (int c = 0; c < 3; c++)
        ch[c] = c0[c] * bw0 + c1[c] * bw1 + c2[c] * bw2;
#pragma unroll
    for (int c = 0; c < 3; c++)
        ch[3 + c] = v0[c] * bw0 + v1[c] * bw1 + v2[c] * bw2;

    float* rend = out;
    float* al   = out + (size_t)NB * 6 * PP;
    float* fo   = al  + (size_t)NB * PP;
    float* zo   = fo  + (size_t)NB * PP;

#pragma unroll
    for (int c = 0; c < 6; c++)
        rend[((size_t)b * 6 + c) * PP + pix] = ch[c] * alpha;
    al[(size_t)b * PP + pix] = alpha;
    fo[(size_t)b * PP + pix] = (float)bf;
    zo[(size_t)b * PP + pix] = bz;
}

extern "C" void kernel_launch(void* const* d_in, const int* in_sizes, int n_in,
                              void* d_out, int out_size) {
    const float* vertices = (const float*)d_in[0];
    const float* tverts   = (const float*)d_in[1];
    const float* tex      = (const float*)d_in[2];
    const float* uv       = (const float*)d_in[3];
    const int*   faces    = (const int*)d_in[4];
    float* out = (float*)d_out;

    pre<<<NB + VCOL_BLKS + ZINIT_BLKS, SORT_THR>>>(tverts, faces, tex, uv);
    dim3 grid(IW / 16, IH / 8, NB * SPLIT);
    raster<<<grid, NTHR>>>();
    shade<<<(NB * PP + 255) / 256, 256>>>(vertices, tverts, faces, out);
}